// round 3
// baseline (speedup 1.0000x reference)
#include <cuda_runtime.h>
#include <cuda_bf16.h>

#define MESH 8
#define NN   512
#define NEx  409
#define NIx  103
#define DD   243
#define BB   512
// K layout: [0,416) own E spikes (409 + pad), [416,544) own I spikes x8192 (103 + pad),
//           [544,960) prev-mesh E spikes (409 + pad). 30 stages of 32.
#define KT      960
#define K_ISEC  416
#define K_PSEC  544
#define ISCALE  8192.0f

// ---------------- device state ----------------
__device__ __align__(16) __nv_bfloat16 g_Wbig[MESH][NN][KT];     // tick GEMM B
__device__ __align__(16) __nv_bfloat16 g_Abuf[2][MESH][BB][KT];  // spike A buffers (ping-pong)
__device__ float g_WinT[MESH][DD][NN];                           // quantized W_in, transposed
__device__ float g_ext[MESH][BB][NN];                            // ext_proj + b_in
__device__ float g_v[MESH][BB][NN];

__device__ __forceinline__ float quantw(float w) {
    float q = rintf(w);                  // round-half-even == jnp.round
    return fminf(7.f, fmaxf(-8.f, q));
}

// ---------------- init kernels ----------------
__global__ void k_zero() {
    long long stride = (long long)gridDim.x * blockDim.x;
    long long i0 = (long long)blockIdx.x * blockDim.x + threadIdx.x;
    __nv_bfloat16* A = &g_Abuf[0][0][0][0];
    long long nA = 2LL * MESH * BB * KT;
    for (long long i = i0; i < nA; i += stride) A[i] = __float2bfloat16(0.f);
    float* V = &g_v[0][0][0];
    long long nV = (long long)MESH * BB * NN;
    for (long long i = i0; i < nV; i += stride) V[i] = 0.f;
}

__global__ void k_build_wbig(const float* __restrict__ W_inter, const float* __restrict__ W_EE,
                             const float* __restrict__ W_EI, const float* __restrict__ W_IE,
                             const float* __restrict__ W_II) {
    long long stride = (long long)gridDim.x * blockDim.x;
    long long tot = (long long)MESH * NN * KT;
    for (long long idx = (long long)blockIdx.x * blockDim.x + threadIdx.x; idx < tot; idx += stride) {
        int k = (int)(idx % KT);
        int n = (int)((idx / KT) % NN);
        int m = (int)(idx / ((long long)KT * NN));
        float w = 0.f;
        if (k < K_ISEC) {                       // E-driven: W_EE / W_EI
            if (k < NEx)
                w = (n < NEx) ? W_EE[((long long)m * NEx + n) * NEx + k]
                              : W_EI[((long long)m * NIx + (n - NEx)) * NEx + k];
            w = quantw(w);
        } else if (k < K_PSEC) {                // I-driven: W_IE / W_II, packed *8192
            int ki = k - K_ISEC;
            if (ki < NIx)
                w = (n < NEx) ? W_IE[((long long)m * NEx + n) * NIx + ki]
                              : W_II[((long long)m * NIx + (n - NEx)) * NIx + ki];
            w = quantw(w) * ISCALE;             // exact in bf16 (power-of-2 scale)
        } else {                                // inter: mesh m receives W_inter[m-1]
            int kp = k - K_PSEC;
            if (kp < NEx) {
                int mp = (m + MESH - 1) % MESH;
                w = W_inter[((long long)mp * NN + n) * NEx + kp];
            }
            w = quantw(w);
        }
        g_Wbig[m][n][k] = __float2bfloat16(w);
    }
}

__global__ void k_build_winT(const float* __restrict__ W_in) {
    long long stride = (long long)gridDim.x * blockDim.x;
    long long tot = (long long)MESH * NN * DD;
    for (long long idx = (long long)blockIdx.x * blockDim.x + threadIdx.x; idx < tot; idx += stride) {
        int d = (int)(idx % DD);
        int n = (int)((idx / DD) % NN);
        int m = (int)(idx / ((long long)DD * NN));
        g_WinT[m][d][n] = quantw(W_in[idx]);
    }
}

// ---------------- ext_proj: serial ascending-d FMA chain per (b,n), + b_in ----------------
// Replicates "single-accumulator k-serial" gemm rounding (cublas simt / Eigen gebp).
#define EXT_BT 16
__global__ void __launch_bounds__(512)
k_ext(const float* __restrict__ X, const float* __restrict__ b_in) {
    __shared__ float sx[EXT_BT][DD];
    const int m  = blockIdx.y;
    const int b0 = blockIdx.x * EXT_BT;
    const int n  = threadIdx.x;
    for (int i = threadIdx.x; i < EXT_BT * DD; i += 512)
        sx[i / DD][i % DD] = X[(long long)(b0 + i / DD) * DD + (i % DD)];
    __syncthreads();
    float acc[EXT_BT];
    #pragma unroll
    for (int bb = 0; bb < EXT_BT; ++bb) acc[bb] = 0.f;
    for (int d = 0; d < DD; ++d) {
        float w = g_WinT[m][d][n];
        #pragma unroll
        for (int bb = 0; bb < EXT_BT; ++bb)
            acc[bb] = __fmaf_rn(sx[bb][d], w, acc[bb]);   // serial in d per (b,n)
    }
    float bi = b_in[m * NN + n];
    #pragma unroll
    for (int bb = 0; bb < EXT_BT; ++bb)
        g_ext[m][b0 + bb][n] = __fadd_rn(acc[bb], bi);
}

// ---------------- mma / ldmatrix / cp.async helpers ----------------
__device__ __forceinline__ void ldm4(unsigned* r, unsigned addr) {
    asm volatile("ldmatrix.sync.aligned.m8n8.x4.shared.b16 {%0,%1,%2,%3}, [%4];\n"
                 : "=r"(r[0]), "=r"(r[1]), "=r"(r[2]), "=r"(r[3]) : "r"(addr));
}
__device__ __forceinline__ void mma16816(float* c, const unsigned* a, unsigned b0, unsigned b1) {
    asm volatile("mma.sync.aligned.m16n8k16.row.col.f32.bf16.bf16.f32 "
                 "{%0,%1,%2,%3}, {%4,%5,%6,%7}, {%8,%9}, {%0,%1,%2,%3};\n"
                 : "+f"(c[0]), "+f"(c[1]), "+f"(c[2]), "+f"(c[3])
                 : "r"(a[0]), "r"(a[1]), "r"(a[2]), "r"(a[3]), "r"(b0), "r"(b1));
}
__device__ __forceinline__ void cpa16(unsigned d, const void* s) {
    asm volatile("cp.async.cg.shared.global [%0], [%1], 16;\n" :: "r"(d), "l"(s));
}

// spike-write helper: maps neuron col -> packed A-buffer k positions
__device__ __forceinline__ void write_spike(int wbuf, int m, int row, int col, float sf) {
    __nv_bfloat16 sb = __float2bfloat16(sf);
    int kown = (col < NEx) ? col : (K_ISEC + col - NEx);
    g_Abuf[wbuf][m][row][kown] = sb;
    if (col < NEx)
        g_Abuf[wbuf][(m + 1) & 7][row][K_PSEC + col] = sb;   // feeds mesh m+1's inter section
}

// ---------------- fused tick GEMM + LIF epilogue ----------------
__global__ void __launch_bounds__(256)
k_gemm(int rbuf, int wbuf, float* __restrict__ dout, float decayI) {
    constexpr int NS = KT / 32;          // 30
    const int m   = blockIdx.z;
    const int bm0 = blockIdx.y * 128;    // batch rows
    const int bn0 = blockIdx.x * 128;    // neuron cols
    const int tid  = threadIdx.x;
    const int lane = tid & 31, warp = tid >> 5;
    const int wm = warp >> 2, wn = warp & 3;   // 2x4 warps, warp tile 64x32

    __shared__ __align__(16) __nv_bfloat16 As[2][128][40];
    __shared__ __align__(16) __nv_bfloat16 Bs[2][128][40];

    const __nv_bfloat16* Ag = &g_Abuf[rbuf][m][bm0][0];
    const __nv_bfloat16* Bg = &g_Wbig[m][bn0][0];
    unsigned asb = (unsigned)__cvta_generic_to_shared(&As[0][0][0]);
    unsigned bsb = (unsigned)__cvta_generic_to_shared(&Bs[0][0][0]);

    auto load_stage = [&](int s, int buf) {
        int k0 = s * 32;
        int ch = tid;
        #pragma unroll
        for (int i = 0; i < 2; ++i) {
            int row = ch >> 2;
            int cc  = (ch & 3) * 8;
            unsigned off = (unsigned)((buf * 128 + row) * 40 + cc) * 2u;
            cpa16(asb + off, Ag + (long long)row * KT + k0 + cc);
            cpa16(bsb + off, Bg + (long long)row * KT + k0 + cc);
            ch += 256;
        }
    };

    float c0[4][4][4], c1[4][4][4];      // group0: E + 8192*I ; group1: inter
    #pragma unroll
    for (int a = 0; a < 4; ++a)
        #pragma unroll
        for (int b = 0; b < 4; ++b)
            #pragma unroll
            for (int f = 0; f < 4; ++f) { c0[a][b][f] = 0.f; c1[a][b][f] = 0.f; }

    load_stage(0, 0);
    asm volatile("cp.async.commit_group;\n");

    const int r15   = lane & 15;
    const int khalf = (lane >> 4) * 8;

    for (int s = 0; s < NS; ++s) {
        if (s + 1 < NS) {
            load_stage(s + 1, (s + 1) & 1);
            asm volatile("cp.async.commit_group;\n");
            asm volatile("cp.async.wait_group 1;\n");
        } else {
            asm volatile("cp.async.wait_group 0;\n");
        }
        __syncthreads();
        int buf = s & 1;
        bool own = (s < (K_PSEC / 32));  // stages 0..16 -> group0, 17..29 -> group1
        #pragma unroll
        for (int kk = 0; kk < 2; ++kk) {
            unsigned a[4][4], bfr[2][4];
            #pragma unroll
            for (int im = 0; im < 4; ++im)
                ldm4(a[im], asb + (unsigned)(((buf * 128 + wm * 64 + im * 16 + r15) * 40)
                                             + kk * 16 + khalf) * 2u);
            #pragma unroll
            for (int ib = 0; ib < 2; ++ib)
                ldm4(bfr[ib], bsb + (unsigned)(((buf * 128 + wn * 32 + ib * 16 + r15) * 40)
                                               + kk * 16 + khalf) * 2u);
            if (own) {
                #pragma unroll
                for (int im = 0; im < 4; ++im)
                    #pragma unroll
                    for (int in = 0; in < 4; ++in) {
                        int ib = in >> 1, sub = in & 1;
                        mma16816(c0[im][in], a[im], bfr[ib][sub], bfr[ib][sub + 2]);
                    }
            } else {
                #pragma unroll
                for (int im = 0; im < 4; ++im)
                    #pragma unroll
                    for (int in = 0; in < 4; ++in) {
                        int ib = in >> 1, sub = in & 1;
                        mma16816(c1[im][in], a[im], bfr[ib][sub], bfr[ib][sub + 2]);
                    }
            }
        }
        __syncthreads();
    }

    // -------- epilogue: unpack integers, replicate reference rounding order --------
    #pragma unroll
    for (int im = 0; im < 4; ++im)
        #pragma unroll
        for (int in = 0; in < 4; ++in)
            #pragma unroll
            for (int f = 0; f < 4; ++f) {
                int row = bm0 + wm * 64 + im * 16 + (lane >> 2) + (f >> 1) * 8;  // batch
                int col = bn0 + wn * 32 + in * 8 + (lane & 3) * 2 + (f & 1);     // neuron
                // decompose packed own-mesh sum (exact integers)
                int ci = (int)c0[im][in][f];
                int r  = ci & 8191;
                int aEi = (r < 4096) ? r : r - 8192;      // E-driven sum, |.| <= 3272
                int aIi = (ci - aEi) >> 13;               // I-driven sum (exact)
                float ext  = g_ext[m][row][col];
                float t1   = __fadd_rn(ext, c1[im][in][f]);       // ext_proj(+b) + inter
                float t2   = __fadd_rn(t1, (float)aEi);           // + E-driven
                float cur  = __fadd_rn(t2, (float)aIi);           // + I-driven
                float vold = g_v[m][row][col];
                float dec  = (col < NEx) ? 0.5f : decayI;
                float vnew = __fadd_rn(__fmul_rn(vold, dec), cur); // XLA: mul then add
                float u    = __fadd_rn(vnew, -1.0f);               // spike(v - VTH)
                bool  sp   = (u >= 0.0f);
                g_v[m][row][col] = sp ? 0.0f : vnew;
                float sf = sp ? 1.0f : 0.0f;
                write_spike(wbuf, m, row, col, sf);
                dout[(long long)row * (MESH * NN) + m * NN + col] += sf;
            }
}

// ---------------- tick 0: zero spikes -> v = 0*decay + ext ----------------
__global__ void k_tick0(float* __restrict__ dout) {
    long long stride = (long long)gridDim.x * blockDim.x;
    long long tot = (long long)MESH * BB * NN;
    for (long long idx = (long long)blockIdx.x * blockDim.x + threadIdx.x; idx < tot; idx += stride) {
        int n = (int)(idx & (NN - 1));
        int b = (int)((idx >> 9) & (BB - 1));
        int m = (int)(idx >> 18);
        float c    = g_ext[m][b][n];
        float vnew = __fadd_rn(0.0f, c);     // 0*decay + c  (normalizes -0)
        float u    = __fadd_rn(vnew, -1.0f);
        bool  sp   = (u >= 0.0f);
        g_v[m][b][n] = sp ? 0.0f : vnew;
        float sf = sp ? 1.0f : 0.0f;
        write_spike(0, m, b, n, sf);
        dout[(long long)b * (MESH * NN) + m * NN + n] = sf;   // init accumulator
    }
}

// ---------------- launch ----------------
extern "C" void kernel_launch(void* const* d_in, const int* in_sizes, int n_in,
                              void* d_out, int out_size) {
    const float* x       = (const float*)d_in[0];
    const float* W_in    = (const float*)d_in[1];
    const float* b_in    = (const float*)d_in[2];
    const float* W_inter = (const float*)d_in[3];
    const float* W_EE    = (const float*)d_in[4];
    const float* W_EI    = (const float*)d_in[5];
    const float* W_IE    = (const float*)d_in[6];
    const float* W_II    = (const float*)d_in[7];
    float* out = (float*)d_out;
    const float decayI = (float)(1.0 - 1.0 / 1.5);   // 0.33333334f, matches f32(py-double)

    k_zero<<<512, 256>>>();
    k_build_wbig<<<2048, 256>>>(W_inter, W_EE, W_EI, W_IE, W_II);
    k_build_winT<<<1024, 256>>>(W_in);
    k_ext<<<dim3(BB / EXT_BT, MESH), 512>>>(x, b_in);
    k_tick0<<<2048, 256>>>(out);

    dim3 grid(4, 4, 8);   // 128 CTAs, single wave
    for (int t = 1; t < 16; ++t)
        k_gemm<<<grid, 256>>>((t - 1) & 1, t & 1, out, decayI);
}

// round 4
// speedup vs baseline: 1.3953x; 1.3953x over previous
#include <cuda_runtime.h>
#include <cuda_bf16.h>

#define MESH 8
#define NN   512
#define NEx  409
#define NIx  103
#define DD   243
#define BB   512
// K layout: [0,416) own E spikes, [416,544) own I spikes x8192, [544,960) prev-mesh E.
#define KT      960
#define K_ISEC  416
#define K_PSEC  544
#define ISCALE  8192.0f
#define NSTG    3
#define NS      (KT / 32)          // 30 k-stages
#define OWN_STG (K_PSEC / 32)      // 17: stages < 17 -> accumulator group 0

// ---------------- device state ----------------
__device__ __align__(16) __nv_bfloat16 g_Wbig[MESH][NN][KT];     // tick GEMM B
__device__ __align__(16) __nv_bfloat16 g_Abuf[2][MESH][BB][KT];  // spike A buffers (ping-pong)
__device__ float g_WinT[MESH][DD][NN];                           // quantized W_in, transposed
__device__ float g_ext[MESH][BB][NN];                            // ext_proj + b_in
__device__ unsigned g_bar;                                       // grid barrier counter

__device__ __forceinline__ float quantw(float w) {
    float q = rintf(w);                  // round-half-even == jnp.round
    return fminf(7.f, fmaxf(-8.f, q));
}

// ---------------- init kernels ----------------
__global__ void k_zero() {
    long long stride = (long long)gridDim.x * blockDim.x;
    long long i0 = (long long)blockIdx.x * blockDim.x + threadIdx.x;
    if (i0 == 0) g_bar = 0u;
    __nv_bfloat16* A = &g_Abuf[0][0][0][0];
    long long nA = 2LL * MESH * BB * KT;
    for (long long i = i0; i < nA; i += stride) A[i] = __float2bfloat16(0.f);
}

__global__ void k_build_wbig(const float* __restrict__ W_inter, const float* __restrict__ W_EE,
                             const float* __restrict__ W_EI, const float* __restrict__ W_IE,
                             const float* __restrict__ W_II) {
    long long stride = (long long)gridDim.x * blockDim.x;
    long long tot = (long long)MESH * NN * KT;
    for (long long idx = (long long)blockIdx.x * blockDim.x + threadIdx.x; idx < tot; idx += stride) {
        int k = (int)(idx % KT);
        int n = (int)((idx / KT) % NN);
        int m = (int)(idx / ((long long)KT * NN));
        float w = 0.f;
        if (k < K_ISEC) {                       // E-driven: W_EE / W_EI
            if (k < NEx)
                w = (n < NEx) ? W_EE[((long long)m * NEx + n) * NEx + k]
                              : W_EI[((long long)m * NIx + (n - NEx)) * NEx + k];
            w = quantw(w);
        } else if (k < K_PSEC) {                // I-driven, packed *8192 (exact in bf16)
            int ki = k - K_ISEC;
            if (ki < NIx)
                w = (n < NEx) ? W_IE[((long long)m * NEx + n) * NIx + ki]
                              : W_II[((long long)m * NIx + (n - NEx)) * NIx + ki];
            w = quantw(w) * ISCALE;
        } else {                                // inter: mesh m receives W_inter[m-1]
            int kp = k - K_PSEC;
            if (kp < NEx) {
                int mp = (m + MESH - 1) % MESH;
                w = W_inter[((long long)mp * NN + n) * NEx + kp];
            }
            w = quantw(w);
        }
        g_Wbig[m][n][k] = __float2bfloat16(w);
    }
}

__global__ void k_build_winT(const float* __restrict__ W_in) {
    long long stride = (long long)gridDim.x * blockDim.x;
    long long tot = (long long)MESH * NN * DD;
    for (long long idx = (long long)blockIdx.x * blockDim.x + threadIdx.x; idx < tot; idx += stride) {
        int d = (int)(idx % DD);
        int n = (int)((idx / DD) % NN);
        int m = (int)(idx / ((long long)DD * NN));
        g_WinT[m][d][n] = quantw(W_in[idx]);
    }
}

// ---------------- ext_proj: serial ascending-d FMA per (b,n) — bitwise == round 3 ----------
#define EXT_BT 16
__global__ void __launch_bounds__(512)
k_ext(const float* __restrict__ X, const float* __restrict__ b_in) {
    __shared__ __align__(16) float sx[DD][EXT_BT];   // transposed: float4-friendly
    const int m  = blockIdx.y;
    const int b0 = blockIdx.x * EXT_BT;
    const int n  = threadIdx.x;
    for (int i = threadIdx.x; i < EXT_BT * DD; i += 512) {
        int bb = i / DD, d = i % DD;
        sx[d][bb] = X[(long long)(b0 + bb) * DD + d];
    }
    __syncthreads();
    float acc[EXT_BT];
    #pragma unroll
    for (int bb = 0; bb < EXT_BT; ++bb) acc[bb] = 0.f;
    for (int d = 0; d < DD; ++d) {
        float w = g_WinT[m][d][n];
        const float4* p = reinterpret_cast<const float4*>(&sx[d][0]);
        #pragma unroll
        for (int q = 0; q < 4; ++q) {
            float4 v4 = p[q];
            acc[q * 4 + 0] = __fmaf_rn(v4.x, w, acc[q * 4 + 0]);
            acc[q * 4 + 1] = __fmaf_rn(v4.y, w, acc[q * 4 + 1]);
            acc[q * 4 + 2] = __fmaf_rn(v4.z, w, acc[q * 4 + 2]);
            acc[q * 4 + 3] = __fmaf_rn(v4.w, w, acc[q * 4 + 3]);
        }
    }
    float bi = b_in[m * NN + n];
    #pragma unroll
    for (int bb = 0; bb < EXT_BT; ++bb)
        g_ext[m][b0 + bb][n] = __fadd_rn(acc[bb], bi);
}

// ---------------- asm helpers ----------------
__device__ __forceinline__ void ldm4(unsigned* r, unsigned addr) {
    asm volatile("ldmatrix.sync.aligned.m8n8.x4.shared.b16 {%0,%1,%2,%3}, [%4];\n"
                 : "=r"(r[0]), "=r"(r[1]), "=r"(r[2]), "=r"(r[3]) : "r"(addr));
}
__device__ __forceinline__ void mma16816(float* c, const unsigned* a, unsigned b0, unsigned b1) {
    asm volatile("mma.sync.aligned.m16n8k16.row.col.f32.bf16.bf16.f32 "
                 "{%0,%1,%2,%3}, {%4,%5,%6,%7}, {%8,%9}, {%0,%1,%2,%3};\n"
                 : "+f"(c[0]), "+f"(c[1]), "+f"(c[2]), "+f"(c[3])
                 : "r"(a[0]), "r"(a[1]), "r"(a[2]), "r"(a[3]), "r"(b0), "r"(b1));
}
__device__ __forceinline__ void cpa16(unsigned d, const void* s) {
    asm volatile("cp.async.cg.shared.global [%0], [%1], 16;\n" :: "r"(d), "l"(s));
}

__device__ __forceinline__ void write_spike(int wbuf, int m, int row, int col, float sf) {
    __nv_bfloat16 sb = __float2bfloat16(sf);
    int kown = (col < NEx) ? col : (K_ISEC + col - NEx);
    g_Abuf[wbuf][m][row][kown] = sb;
    if (col < NEx)
        g_Abuf[wbuf][(m + 1) & 7][row][K_PSEC + col] = sb;
}

// software grid barrier: all spikes gpu-visible, then release/acquire on counter
__device__ __forceinline__ void grid_barrier(unsigned phase) {
    __threadfence();          // every thread: make its spike STGs gpu-visible
    __syncthreads();
    if (threadIdx.x == 0) {
        asm volatile("red.release.gpu.global.add.u32 [%0], %1;"
                     :: "l"(&g_bar), "r"(1u) : "memory");
        unsigned target = phase * 128u;
        unsigned v;
        do {
            asm volatile("ld.acquire.gpu.global.u32 %0, [%1];"
                         : "=r"(v) : "l"(&g_bar) : "memory");
            if (v < target) __nanosleep(64);
        } while (v < target);
    }
    __syncthreads();
}

// ---------------- persistent reservoir kernel ----------------
// smem layout (dynamic): As[NSTG][128][40] | Bs[NSTG][128][40] | v[128][132] f32
//                        | ext[128][132] f32 | acc[128][128] u8
#define SM_AS   0
#define SM_BS   (NSTG * 128 * 40 * 2)
#define SM_V    (2 * NSTG * 128 * 40 * 2)
#define SM_E    (SM_V + 128 * 132 * 4)
#define SM_ACC  (SM_E + 128 * 132 * 4)
#define SM_TOT  (SM_ACC + 128 * 128)

__global__ void __launch_bounds__(256, 1)
k_persist(float* __restrict__ dout, float decayI) {
    extern __shared__ __align__(16) char sm[];
    float*         sv   = (float*)(sm + SM_V);
    float*         se   = (float*)(sm + SM_E);
    unsigned char* sacc = (unsigned char*)(sm + SM_ACC);

    const int m   = blockIdx.z;
    const int bm0 = blockIdx.y * 128;
    const int bn0 = blockIdx.x * 128;
    const int tid  = threadIdx.x;
    const int lane = tid & 31, warp = tid >> 5;
    const int wm = warp >> 2, wn = warp & 3;

    unsigned asb = (unsigned)__cvta_generic_to_shared(sm + SM_AS);
    unsigned bsb = (unsigned)__cvta_generic_to_shared(sm + SM_BS);

    // load ext tile into smem (held all 16 ticks)
    for (int i = tid; i < 128 * 128; i += 256) {
        int r = i >> 7, c = i & 127;
        se[r * 132 + c] = g_ext[m][bm0 + r][bn0 + c];
    }
    __syncthreads();

    // -------- tick 0: v = 0 + ext --------
    for (int i = tid; i < 128 * 128; i += 256) {
        int r = i >> 7, c = i & 127;
        float cc   = se[r * 132 + c];
        float vnew = __fadd_rn(0.0f, cc);
        float u    = __fadd_rn(vnew, -1.0f);
        bool  sp   = (u >= 0.0f);
        sv[r * 132 + c] = sp ? 0.0f : vnew;
        sacc[i] = sp ? 1 : 0;
        write_spike(0, m, bm0 + r, bn0 + c, sp ? 1.0f : 0.0f);
    }
    grid_barrier(1);

    const int r15   = lane & 15;
    const int khalf = (lane >> 4) * 8;

    for (int t = 1; t < 16; ++t) {
        const int rbuf = (t - 1) & 1, wbuf = t & 1;
        const __nv_bfloat16* Ag = &g_Abuf[rbuf][m][bm0][0];
        const __nv_bfloat16* Bg = &g_Wbig[m][bn0][0];

        auto load_stage = [&](int s, int buf) {
            int k0 = s * 32;
            int ch = tid;
            #pragma unroll
            for (int i = 0; i < 2; ++i) {
                int row = ch >> 2;
                int cc  = (ch & 3) * 8;
                unsigned off = (unsigned)((buf * 128 + row) * 40 + cc) * 2u;
                cpa16(asb + off, Ag + (long long)row * KT + k0 + cc);
                cpa16(bsb + off, Bg + (long long)row * KT + k0 + cc);
                ch += 256;
            }
        };

        float c0[4][4][4], c1[4][4][4];
        #pragma unroll
        for (int a = 0; a < 4; ++a)
            #pragma unroll
            for (int b = 0; b < 4; ++b)
                #pragma unroll
                for (int f = 0; f < 4; ++f) { c0[a][b][f] = 0.f; c1[a][b][f] = 0.f; }

        load_stage(0, 0);
        asm volatile("cp.async.commit_group;\n");
        load_stage(1, 1);
        asm volatile("cp.async.commit_group;\n");

        for (int s = 0; s < NS; ++s) {
            if (s + 1 < NS) asm volatile("cp.async.wait_group 1;\n");
            else            asm volatile("cp.async.wait_group 0;\n");
            __syncthreads();
            if (s + 2 < NS) {
                load_stage(s + 2, (s + 2) % NSTG);
                asm volatile("cp.async.commit_group;\n");
            }
            int  buf = s % NSTG;
            bool own = (s < OWN_STG);
            #pragma unroll
            for (int kk = 0; kk < 2; ++kk) {
                unsigned a[4][4], bfr[2][4];
                #pragma unroll
                for (int im = 0; im < 4; ++im)
                    ldm4(a[im], asb + (unsigned)(((buf * 128 + wm * 64 + im * 16 + r15) * 40)
                                                 + kk * 16 + khalf) * 2u);
                #pragma unroll
                for (int ib = 0; ib < 2; ++ib)
                    ldm4(bfr[ib], bsb + (unsigned)(((buf * 128 + wn * 32 + ib * 16 + r15) * 40)
                                                   + kk * 16 + khalf) * 2u);
                if (own) {
                    #pragma unroll
                    for (int im = 0; im < 4; ++im)
                        #pragma unroll
                        for (int in = 0; in < 4; ++in) {
                            int ib = in >> 1, sub = in & 1;
                            mma16816(c0[im][in], a[im], bfr[ib][sub], bfr[ib][sub + 2]);
                        }
                } else {
                    #pragma unroll
                    for (int im = 0; im < 4; ++im)
                        #pragma unroll
                        for (int in = 0; in < 4; ++in) {
                            int ib = in >> 1, sub = in & 1;
                            mma16816(c1[im][in], a[im], bfr[ib][sub], bfr[ib][sub + 2]);
                        }
                }
            }
            __syncthreads();
        }

        // -------- epilogue: identical arithmetic to round 3 (bitwise) --------
        #pragma unroll
        for (int im = 0; im < 4; ++im)
            #pragma unroll
            for (int in = 0; in < 4; ++in)
                #pragma unroll
                for (int f = 0; f < 4; ++f) {
                    int r = wm * 64 + im * 16 + (lane >> 2) + (f >> 1) * 8;   // local batch row
                    int c = wn * 32 + in * 8 + (lane & 3) * 2 + (f & 1);      // local neuron col
                    int col = bn0 + c;
                    int ci = (int)c0[im][in][f];
                    int rr = ci & 8191;
                    int aEi = (rr < 4096) ? rr : rr - 8192;
                    int aIi = (ci - aEi) >> 13;
                    float ext  = se[r * 132 + c];
                    float t1   = __fadd_rn(ext, c1[im][in][f]);
                    float t2   = __fadd_rn(t1, (float)aEi);
                    float cur  = __fadd_rn(t2, (float)aIi);
                    float vold = sv[r * 132 + c];
                    float dec  = (col < NEx) ? 0.5f : decayI;
                    float vnew = __fadd_rn(__fmul_rn(vold, dec), cur);
                    float u    = __fadd_rn(vnew, -1.0f);
                    bool  sp   = (u >= 0.0f);
                    sv[r * 132 + c] = sp ? 0.0f : vnew;
                    sacc[r * 128 + c] = (unsigned char)(sacc[r * 128 + c] + (sp ? 1 : 0));
                    write_spike(wbuf, m, bm0 + r, col, sp ? 1.0f : 0.0f);
                }

        if (t < 15) grid_barrier((unsigned)(t + 1));
    }

    __syncthreads();
    for (int i = tid; i < 128 * 128; i += 256) {
        int r = i >> 7, c = i & 127;
        dout[(long long)(bm0 + r) * (MESH * NN) + m * NN + bn0 + c] = (float)sacc[i];
    }
}

// ---------------- launch ----------------
extern "C" void kernel_launch(void* const* d_in, const int* in_sizes, int n_in,
                              void* d_out, int out_size) {
    const float* x       = (const float*)d_in[0];
    const float* W_in    = (const float*)d_in[1];
    const float* b_in    = (const float*)d_in[2];
    const float* W_inter = (const float*)d_in[3];
    const float* W_EE    = (const float*)d_in[4];
    const float* W_EI    = (const float*)d_in[5];
    const float* W_IE    = (const float*)d_in[6];
    const float* W_II    = (const float*)d_in[7];
    float* out = (float*)d_out;
    const float decayI = (float)(1.0 - 1.0 / 1.5);

    static int smem_set = 0;
    if (!smem_set) {
        cudaFuncSetAttribute(k_persist, cudaFuncAttributeMaxDynamicSharedMemorySize, SM_TOT);
        smem_set = 1;
    }

    k_zero<<<512, 256>>>();
    k_build_wbig<<<2048, 256>>>(W_inter, W_EE, W_EI, W_IE, W_II);
    k_build_winT<<<1024, 256>>>(W_in);
    k_ext<<<dim3(BB / EXT_BT, MESH), 512>>>(x, b_in);

    dim3 grid(4, 4, 8);   // 128 CTAs, 1 per SM, co-resident
    k_persist<<<grid, 256, SM_TOT>>>(out, decayI);
}